// round 1
// baseline (speedup 1.0000x reference)
#include <cuda_runtime.h>
#include <math.h>
#include <stdint.h>

#define BATCH 32768
#define FBDIM 512

typedef unsigned long long ull;

// ---------------- scratch (device globals; no allocation allowed) ----------------
__device__ float g_c1[BATCH * 300];   // phase-1 mish collect
__device__ float g_c2[BATCH * 600];   // phase-2 mish collect
__device__ float g_c3[BATCH * 600];   // phase-3 mish collect
__device__ float g_carA[BATCH * 300]; // carry ping
__device__ float g_carB[BATCH * 100]; // carry pong
__device__ double g_stats[3][2];      // per-phase {sum, sumsq} of mish outputs
__device__ float g_affine[3][2];      // per-phase {alpha, beta} for folded BN

// ---------------- helpers ----------------
__device__ __forceinline__ ull splat2(float a) {
    ull r;
    asm("mov.b64 %0, {%1, %1};" : "=l"(r) : "f"(a));
    return r;
}
__device__ __forceinline__ void ffma2(ull &c, ull a, ull b) {
    asm("fma.rn.f32x2 %0, %1, %2, %0;" : "+l"(c) : "l"(a), "l"(b));
}
__device__ __forceinline__ float2 unpack2(ull v) {
    float2 f;
    asm("mov.b64 {%0, %1}, %2;" : "=f"(f.x), "=f"(f.y) : "l"(v));
    return f;
}
__device__ __forceinline__ float mishf(float v) {
    // v >= 0 (post-relu): softplus(v) = v + log1p(exp(-v)) is stable
    float sp = v + log1pf(expf(-v));
    return v * tanhf(sp);
}

__global__ void zero_stats_kernel() {
    if (threadIdx.x < 6) ((double *)g_stats)[threadIdx.x] = 0.0;
}

__global__ void finalize_kernel(int p, const float *__restrict__ g,
                                const float *__restrict__ b, double count) {
    double mean = g_stats[p][0] / count;
    double var = g_stats[p][1] / count - mean * mean;
    double alpha = (double)g[0] / sqrt(var + 1e-5);
    g_affine[p][0] = (float)alpha;
    g_affine[p][1] = (float)((double)b[0] - mean * alpha);
}

// ---------------- fused GEMM + relu + split(mish/collect | carry) + stats ----------------
#define BM 128
#define BN 128
#define BK 16
#define ASTR 132  // padded A-tile stride (floats)

__global__ __launch_bounds__(256, 2) void gemm_split_kernel(
    const float *__restrict__ A, int lda,
    const float *__restrict__ W, const float *__restrict__ bias,
    int K, int N, int OUT,
    float *__restrict__ collect, int ldc,
    float *__restrict__ carry, int ldcar,
    int stats_phase, int aff_phase) {
    __shared__ float As[BK * ASTR];
    __shared__ float Bs[BK * BN];
    __shared__ double red[16];

    const int t = threadIdx.x;
    const int tx = t & 15;       // col group (0..15)
    const int ty = t >> 4;       // row group (0..15)
    const int rowBase = blockIdx.y * BM;
    const int colBase = blockIdx.x * BN;

    float alpha = 1.f, beta = 0.f;
    if (aff_phase >= 0) { alpha = g_affine[aff_phase][0]; beta = g_affine[aff_phase][1]; }

    const int lr = t >> 1;          // 0..127 (loader row / weight row)
    const int lk = (t & 1) * 8;     // 0 or 8

    ull acc[8][4];
#pragma unroll
    for (int i = 0; i < 8; i++)
#pragma unroll
        for (int j = 0; j < 4; j++) acc[i][j] = 0ULL;

    const float *Arow = A + (size_t)(rowBase + lr) * lda;
    const bool wvalid = (colBase + lr) < N;
    const float *Wrow = wvalid ? (W + (size_t)(colBase + lr) * K) : W;

    for (int kt = 0; kt < K; kt += BK) {
#pragma unroll
        for (int u = 0; u < 8; u++) {
            int k = kt + lk + u;
            float v = 0.f;
            if (k < K) v = alpha * Arow[k] + beta;
            As[(lk + u) * ASTR + lr] = v;
        }
#pragma unroll
        for (int u = 0; u < 8; u++) {
            int k = kt + lk + u;
            float v = (wvalid && k < K) ? Wrow[k] : 0.f;
            Bs[(lk + u) * BN + lr] = v;
        }
        __syncthreads();
#pragma unroll
        for (int kk = 0; kk < BK; kk++) {
            float4 a0 = *(const float4 *)&As[kk * ASTR + ty * 8];
            float4 a1 = *(const float4 *)&As[kk * ASTR + ty * 8 + 4];
            ulonglong2 b0 = *(const ulonglong2 *)&Bs[kk * BN + tx * 8];
            ulonglong2 b1 = *(const ulonglong2 *)&Bs[kk * BN + tx * 8 + 4];
            ull bp0 = b0.x, bp1 = b0.y, bp2 = b1.x, bp3 = b1.y;
            float av[8] = {a0.x, a0.y, a0.z, a0.w, a1.x, a1.y, a1.z, a1.w};
#pragma unroll
            for (int i = 0; i < 8; i++) {
                ull ap = splat2(av[i]);
                ffma2(acc[i][0], ap, bp0);
                ffma2(acc[i][1], ap, bp1);
                ffma2(acc[i][2], ap, bp2);
                ffma2(acc[i][3], ap, bp3);
            }
        }
        __syncthreads();
    }

    // ---- epilogue: bias + relu + split into mish/collect (with stats) or carry ----
    double lsum = 0.0, lsq = 0.0;
    const int r0 = rowBase + ty * 8;
    const int c0 = colBase + tx * 8;
    float bcol[8];
#pragma unroll
    for (int j = 0; j < 8; j++) {
        int c = c0 + j;
        bcol[j] = (c < N) ? bias[c] : 0.f;
    }

#pragma unroll
    for (int i = 0; i < 8; i++) {
        int r = r0 + i;
#pragma unroll
        for (int j = 0; j < 4; j++) {
            float2 v2 = unpack2(acc[i][j]);
            float vv0 = v2.x, vv1 = v2.y;
#pragma unroll
            for (int h = 0; h < 2; h++) {
                int c = c0 + j * 2 + h;
                if (c < N) {
                    float v = (h == 0 ? vv0 : vv1) + bcol[j * 2 + h];
                    v = fmaxf(v, 0.f);
                    if (c < OUT) {
                        float m = mishf(v);
                        collect[(size_t)r * ldc + c] = m;
                        lsum += (double)m;
                        lsq += (double)m * (double)m;
                    } else {
                        carry[(size_t)r * ldcar + (c - OUT)] = v;
                    }
                }
            }
        }
    }

    // ---- CTA stats reduction -> double atomics ----
#pragma unroll
    for (int off = 16; off > 0; off >>= 1) {
        lsum += __shfl_down_sync(0xffffffffu, lsum, off);
        lsq += __shfl_down_sync(0xffffffffu, lsq, off);
    }
    if ((t & 31) == 0) {
        red[t >> 5] = lsum;
        red[8 + (t >> 5)] = lsq;
    }
    __syncthreads();
    if (t == 0) {
        double s = 0.0, q = 0.0;
#pragma unroll
        for (int w = 0; w < 8; w++) { s += red[w]; q += red[8 + w]; }
        atomicAdd(&g_stats[stats_phase][0], s);
        atomicAdd(&g_stats[stats_phase][1], q);
    }
}

// ---------------- final: fc (600->512) + sigmoid + codebook quantize ----------------
__global__ __launch_bounds__(256, 2) void fc_quant_kernel(
    const float *__restrict__ A, int lda,
    const float *__restrict__ W, const float *__restrict__ bias,
    const float *__restrict__ codebook,
    float *__restrict__ out, int aff_phase) {
    __shared__ float As[BK * ASTR];
    __shared__ float Bs[BK * BN];
    __shared__ float cbs[FBDIM * 8];

    const int t = threadIdx.x;
    const int tx = t & 15;
    const int ty = t >> 4;
    const int rowBase = blockIdx.y * BM;
    const int colBase = blockIdx.x * BN;
    const int K = 600, N = FBDIM;

    const float alpha = g_affine[aff_phase][0];
    const float beta = g_affine[aff_phase][1];

    for (int i = t; i < FBDIM * 8; i += 256) cbs[i] = codebook[i];

    const int lr = t >> 1;
    const int lk = (t & 1) * 8;

    ull acc[8][4];
#pragma unroll
    for (int i = 0; i < 8; i++)
#pragma unroll
        for (int j = 0; j < 4; j++) acc[i][j] = 0ULL;

    const float *Arow = A + (size_t)(rowBase + lr) * lda;
    const float *Wrow = W + (size_t)(colBase + lr) * K;

    for (int kt = 0; kt < K; kt += BK) {
#pragma unroll
        for (int u = 0; u < 8; u++) {
            int k = kt + lk + u;
            float v = 0.f;
            if (k < K) v = alpha * Arow[k] + beta;
            As[(lk + u) * ASTR + lr] = v;
        }
#pragma unroll
        for (int u = 0; u < 8; u++) {
            int k = kt + lk + u;
            Bs[(lk + u) * BN + lr] = (k < K) ? Wrow[k] : 0.f;
        }
        __syncthreads();
#pragma unroll
        for (int kk = 0; kk < BK; kk++) {
            float4 a0 = *(const float4 *)&As[kk * ASTR + ty * 8];
            float4 a1 = *(const float4 *)&As[kk * ASTR + ty * 8 + 4];
            ulonglong2 b0 = *(const ulonglong2 *)&Bs[kk * BN + tx * 8];
            ulonglong2 b1 = *(const ulonglong2 *)&Bs[kk * BN + tx * 8 + 4];
            ull bp0 = b0.x, bp1 = b0.y, bp2 = b1.x, bp3 = b1.y;
            float av[8] = {a0.x, a0.y, a0.z, a0.w, a1.x, a1.y, a1.z, a1.w};
#pragma unroll
            for (int i = 0; i < 8; i++) {
                ull ap = splat2(av[i]);
                ffma2(acc[i][0], ap, bp0);
                ffma2(acc[i][1], ap, bp1);
                ffma2(acc[i][2], ap, bp2);
                ffma2(acc[i][3], ap, bp3);
            }
        }
        __syncthreads();
    }

    const int r0 = rowBase + ty * 8;
    const int c0 = colBase + tx * 8;
    float bcol[8];
#pragma unroll
    for (int j = 0; j < 8; j++) bcol[j] = bias[c0 + j];

    const size_t seg = (size_t)BATCH * FBDIM;
#pragma unroll
    for (int i = 0; i < 8; i++) {
        int r = r0 + i;
#pragma unroll
        for (int j = 0; j < 4; j++) {
            float2 v2 = unpack2(acc[i][j]);
            float vv[2] = {v2.x, v2.y};
#pragma unroll
            for (int h = 0; h < 2; h++) {
                int c = c0 + j * 2 + h;
                float v = vv[h] + bcol[j * 2 + h];
                float o = 1.f / (1.f + expf(-v));
                const float *cb = &cbs[c * 8];
                float mind = 3.402823466e38f;
                float q = -3.402823466e38f;
#pragma unroll
                for (int e = 0; e < 8; e++) {
                    float cv = cb[e];
                    float df = o - cv;
                    float d = df * df;
                    if (d < mind) { mind = d; q = cv; }
                    else if (d == mind) { q = fmaxf(q, cv); }
                }
                float strite = o + (q - o);  // mirror reference arithmetic
                size_t idx = (size_t)r * FBDIM + c;
                out[idx] = strite;
                out[seg + idx] = q;
                out[2 * seg + idx] = o;
            }
        }
    }
}

// ---------------- launch ----------------
extern "C" void kernel_launch(void *const *d_in, const int *in_sizes, int n_in,
                              void *d_out, int out_size) {
    (void)in_sizes; (void)n_in; (void)out_size;
    const float *x = (const float *)d_in[0];
    const float *w[9], *bb[9];
    for (int i = 0; i < 9; i++) {
        w[i] = (const float *)d_in[1 + 2 * i];
        bb[i] = (const float *)d_in[2 + 2 * i];
    }
    const float *bn_g[3] = {(const float *)d_in[19], (const float *)d_in[21],
                            (const float *)d_in[23]};
    const float *bn_b[3] = {(const float *)d_in[20], (const float *)d_in[22],
                            (const float *)d_in[24]};
    const float *fc_w = (const float *)d_in[25];
    const float *fc_b = (const float *)d_in[26];
    const float *cbk = (const float *)d_in[27];
    float *out = (float *)d_out;

    float *c1, *c2, *c3, *cA, *cB;
    cudaGetSymbolAddress((void **)&c1, g_c1);
    cudaGetSymbolAddress((void **)&c2, g_c2);
    cudaGetSymbolAddress((void **)&c3, g_c3);
    cudaGetSymbolAddress((void **)&cA, g_carA);
    cudaGetSymbolAddress((void **)&cB, g_carB);

    const dim3 thr(256);
    auto grid = [](int N) { return dim3((N + BN - 1) / BN, BATCH / BM); };

    zero_stats_kernel<<<1, 32>>>();

    // phase 1: 24 -> 300 (out 150) -> 150 (out 100) -> 50 (out 50)
    gemm_split_kernel<<<grid(300), thr>>>(x, 24, w[0], bb[0], 24, 300, 150, c1, 300, cA, 150, 0, -1);
    gemm_split_kernel<<<grid(150), thr>>>(cA, 150, w[1], bb[1], 150, 150, 100, c1 + 150, 300, cB, 50, 0, -1);
    gemm_split_kernel<<<grid(50), thr>>>(cB, 50, w[2], bb[2], 50, 50, 50, c1 + 250, 300, nullptr, 0, 0, -1);
    finalize_kernel<<<1, 1>>>(0, bn_g[0], bn_b[0], (double)BATCH * 300.0);

    // phase 2: 300 -> 600 (out 300) -> 300 (out 200) -> 100 (out 100)
    gemm_split_kernel<<<grid(600), thr>>>(c1, 300, w[3], bb[3], 300, 600, 300, c2, 600, cA, 300, 1, 0);
    gemm_split_kernel<<<grid(300), thr>>>(cA, 300, w[4], bb[4], 300, 300, 200, c2 + 300, 600, cB, 100, 1, -1);
    gemm_split_kernel<<<grid(100), thr>>>(cB, 100, w[5], bb[5], 100, 100, 100, c2 + 500, 600, nullptr, 0, 1, -1);
    finalize_kernel<<<1, 1>>>(1, bn_g[1], bn_b[1], (double)BATCH * 600.0);

    // phase 3: 600 -> 600 (out 300) -> 300 (out 200) -> 100 (out 100)
    gemm_split_kernel<<<grid(600), thr>>>(c2, 600, w[6], bb[6], 600, 600, 300, c3, 600, cA, 300, 2, 1);
    gemm_split_kernel<<<grid(300), thr>>>(cA, 300, w[7], bb[7], 300, 300, 200, c3 + 300, 600, cB, 100, 2, -1);
    gemm_split_kernel<<<grid(100), thr>>>(cB, 100, w[8], bb[8], 100, 100, 100, c3 + 500, 600, nullptr, 0, 2, -1);
    finalize_kernel<<<1, 1>>>(2, bn_g[2], bn_b[2], (double)BATCH * 600.0);

    // fc + sigmoid + codebook quantize + write 3 output segments
    fc_quant_kernel<<<grid(FBDIM), thr>>>(c3, 600, fc_w, fc_b, cbk, out, 2);
}

// round 4
// speedup vs baseline: 2.1662x; 2.1662x over previous
#include <cuda_runtime.h>
#include <math.h>
#include <stdint.h>

#define BATCH 32768
#define FBDIM 512
#define BM 128
#define BN 64
#define BK 16
#define BSTR 20   // Bs row stride in floats (bank-conflict-free for LDS.128)
#define NTHR 256
#define LDCARA 304
#define LDCARB 104

typedef unsigned long long ull;

// ---------------- scratch (device globals; no allocation allowed) ----------------
__device__ float g_c1[BATCH * 300];
__device__ float g_c2[BATCH * 600];
__device__ float g_c3[BATCH * 600];
__device__ float g_carA[BATCH * LDCARA];  // carry ping (max width 300, padded)
__device__ float g_carB[BATCH * LDCARB];  // carry pong (max width 100, padded)
__device__ double g_stats[3][2];
__device__ float g_affine[3][2];
__device__ float g_ws[1712];              // rowsums: w3[0:600], w6[600:1200], fc[1200:1712]

// ---------------- helpers ----------------
__device__ __forceinline__ void ffma2(ull &c, ull a, ull b) {
    asm("fma.rn.f32x2 %0, %1, %2, %0;" : "+l"(c) : "l"(a), "l"(b));
}
__device__ __forceinline__ float2 unpack2(ull v) {
    float2 f;
    asm("mov.b64 {%0, %1}, %2;" : "=f"(f.x), "=f"(f.y) : "l"(v));
    return f;
}
__device__ __forceinline__ float mishf(float v) {
    float sp = v + log1pf(expf(-v));   // v >= 0 post-relu: stable
    return v * tanhf(sp);
}
__device__ __forceinline__ void cpa16(uint32_t dst, const float *src, int srcbytes) {
    asm volatile("cp.async.cg.shared.global [%0], [%1], 16, %2;\n"
                 :: "r"(dst), "l"(src), "r"(srcbytes));
}
__device__ __forceinline__ void cpa8(uint32_t dst, const float *src, int srcbytes) {
    asm volatile("cp.async.ca.shared.global [%0], [%1], 8, %2;\n"
                 :: "r"(dst), "l"(src), "r"(srcbytes));
}
__device__ __forceinline__ void cp_commit() {
    asm volatile("cp.async.commit_group;\n" ::: "memory");
}
__device__ __forceinline__ void cp_wait0() {
    asm volatile("cp.async.wait_group 0;\n" ::: "memory");
}
__device__ __forceinline__ int clampi(int v, int lo, int hi) {
    return v < lo ? lo : (v > hi ? hi : v);
}

// ---------------- setup: zero stats + weight rowsums ----------------
__global__ void setup_kernel(const float *__restrict__ w3, const float *__restrict__ w6,
                             const float *__restrict__ wfc) {
    int b = blockIdx.x;
    if (b == 0 && threadIdx.x < 6) ((double *)g_stats)[threadIdx.x] = 0.0;
    const float *src; int K;
    if (b < 600)       { src = w3 + (size_t)b * 300;          K = 300; }
    else if (b < 1200) { src = w6 + (size_t)(b - 600) * 600;  K = 600; }
    else               { src = wfc + (size_t)(b - 1200) * 600; K = 600; }
    float s = 0.f;
    for (int k = threadIdx.x; k < K; k += 128) s += src[k];
#pragma unroll
    for (int o = 16; o; o >>= 1) s += __shfl_down_sync(0xffffffffu, s, o);
    __shared__ float sm[4];
    if ((threadIdx.x & 31) == 0) sm[threadIdx.x >> 5] = s;
    __syncthreads();
    if (threadIdx.x == 0) g_ws[b] = sm[0] + sm[1] + sm[2] + sm[3];
}

__global__ void finalize_kernel(int p, const float *__restrict__ g,
                                const float *__restrict__ b, double count) {
    double mean = g_stats[p][0] / count;
    double var = g_stats[p][1] / count - mean * mean;
    double alpha = (double)g[0] / sqrt(var + 1e-5);
    g_affine[p][0] = (float)alpha;
    g_affine[p][1] = (float)((double)b[0] - mean * alpha);
}

// ---------------- fused GEMM (cp.async double-buffered) + relu + split + stats ----------------
__global__ __launch_bounds__(NTHR, 2) void gemm_split_kernel(
    const float *__restrict__ A, int lda,
    const float *__restrict__ W, const float *__restrict__ bias,
    const float *__restrict__ ws,
    int K, int N, int OUT,
    float *__restrict__ collect, int ldc,
    float *__restrict__ carry, int ldcar,
    int stats_phase, int aff_phase, int useCp16) {
    __shared__ __align__(16) float As[2][BM * BK];
    __shared__ __align__(16) float Bs[2][BN * BSTR];
    __shared__ double red[16];

    const int t = threadIdx.x;
    const int tx = t & 15;
    const int ty = t >> 4;
    const int rowBase = blockIdx.y * BM;
    const int colBase = blockIdx.x * BN;

    // loader mapping
    const int ar = t >> 1;                  // A row 0..127, 2 chunks each
    const int ac = (t & 1) * 2;
    const float *Abase = A + (size_t)(rowBase + ar) * lda;
    const int br = t >> 2;                  // B row 0..63
    const int n_b = colBase + br;
    const bool bv = n_b < N;
    const float *Wrow = W + (size_t)(bv ? n_b : 0) * K;

    const uint32_t sA = (uint32_t)__cvta_generic_to_shared(&As[0][0]);
    const uint32_t sB = (uint32_t)__cvta_generic_to_shared(&Bs[0][0]);
    const int bufAB = BM * BK * 4;
    const int bufBB = BN * BSTR * 4;

    ull acc[8][4];
#pragma unroll
    for (int i = 0; i < 8; i++)
#pragma unroll
        for (int j = 0; j < 4; j++) acc[i][j] = 0ULL;

    const int T = (K + BK - 1) / BK;

    // ---- tile issue ----
    auto issue = [&](int kt, int buf) {
#pragma unroll
        for (int u = 0; u < 2; ++u) {
            int ch = ac + u;
            int k0 = kt + ch * 4;
            int sb = clampi((K - k0) * 4, 0, 16);
            const float *src = sb > 0 ? (Abase + k0) : A;
            cpa16(sA + buf * bufAB + (ar * BK + ch * 4) * 4, src, sb);
        }
        if (useCp16) {
            int ch = t & 3;
            int k0 = kt + ch * 4;
            int sb = bv ? clampi((K - k0) * 4, 0, 16) : 0;
            const float *src = sb > 0 ? (Wrow + k0) : W;
            cpa16(sB + buf * bufBB + (br * BSTR + ch * 4) * 4, src, sb);
        } else {
#pragma unroll
            for (int u = 0; u < 2; ++u) {
                int ch = (t & 3) * 2 + u;
                int k0 = kt + ch * 2;
                int sb = bv ? clampi((K - k0) * 4, 0, 8) : 0;
                const float *src = sb > 0 ? (Wrow + k0) : W;
                cpa8(sB + buf * bufBB + (br * BSTR + ch * 2) * 4, src, sb);
            }
        }
        cp_commit();
    };

    issue(0, 0);
    for (int it = 0; it < T; ++it) {
        cp_wait0();
        __syncthreads();
        if (it + 1 < T) issue((it + 1) * BK, (it + 1) & 1);
        const float *as = As[it & 1];
        const float *bs = Bs[it & 1];
#pragma unroll
        for (int k4 = 0; k4 < 4; ++k4) {
            ulonglong2 b[4];
#pragma unroll
            for (int j = 0; j < 4; ++j)
                b[j] = *(const ulonglong2 *)&bs[(tx + 16 * j) * BSTR + k4 * 4];
#pragma unroll
            for (int i = 0; i < 8; ++i) {
                ulonglong2 a = *(const ulonglong2 *)&as[(ty * 8 + i) * BK + k4 * 4];
#pragma unroll
                for (int j = 0; j < 4; ++j) {
                    ffma2(acc[i][j], a.x, b[j].x);
                    ffma2(acc[i][j], a.y, b[j].y);
                }
            }
        }
    }

    // ---- epilogue ----
    float alpha = 1.f, beta = 0.f;
    if (aff_phase >= 0) { alpha = g_affine[aff_phase][0]; beta = g_affine[aff_phase][1]; }

    int cc[4]; bool cvl[4]; float effb[4];
#pragma unroll
    for (int j = 0; j < 4; ++j) {
        cc[j] = colBase + tx + 16 * j;
        cvl[j] = cc[j] < N;
        effb[j] = cvl[j] ? (bias[cc[j]] + (ws ? beta * ws[cc[j]] : 0.f)) : 0.f;
    }

    double lsum = 0.0, lsq = 0.0;
    const int r0 = rowBase + ty * 8;
#pragma unroll
    for (int i = 0; i < 8; ++i) {
        int r = r0 + i;
#pragma unroll
        for (int j = 0; j < 4; ++j) {
            if (!cvl[j]) continue;
            float2 p = unpack2(acc[i][j]);
            float v = fmaf(alpha, p.x + p.y, effb[j]);
            v = fmaxf(v, 0.f);
            if (cc[j] < OUT) {
                float m = mishf(v);
                collect[(size_t)r * ldc + cc[j]] = m;
                lsum += (double)m;
                lsq += (double)m * (double)m;
            } else {
                carry[(size_t)r * ldcar + (cc[j] - OUT)] = v;
            }
        }
    }

#pragma unroll
    for (int off = 16; off > 0; off >>= 1) {
        lsum += __shfl_down_sync(0xffffffffu, lsum, off);
        lsq += __shfl_down_sync(0xffffffffu, lsq, off);
    }
    if ((t & 31) == 0) { red[t >> 5] = lsum; red[8 + (t >> 5)] = lsq; }
    __syncthreads();
    if (t == 0) {
        double s = 0.0, q = 0.0;
#pragma unroll
        for (int w = 0; w < 8; w++) { s += red[w]; q += red[8 + w]; }
        atomicAdd(&g_stats[stats_phase][0], s);
        atomicAdd(&g_stats[stats_phase][1], q);
    }
}

// ---------------- final: fc (600->512) + sigmoid + codebook quantize ----------------
__global__ __launch_bounds__(NTHR, 2) void fc_quant_kernel(
    const float *__restrict__ A, int lda,
    const float *__restrict__ W, const float *__restrict__ bias,
    const float *__restrict__ ws,
    const float *__restrict__ codebook,
    float *__restrict__ out) {
    __shared__ __align__(16) float As[2][BM * BK];
    __shared__ __align__(16) float Bs[2][BN * BSTR];
    __shared__ float cbs[BN * 8];

    const int t = threadIdx.x;
    const int tx = t & 15;
    const int ty = t >> 4;
    const int rowBase = blockIdx.y * BM;
    const int colBase = blockIdx.x * BN;
    const int K = 600, N = FBDIM;

    for (int i = t; i < BN * 8; i += NTHR) cbs[i] = codebook[colBase * 8 + i];

    const int ar = t >> 1;
    const int ac = (t & 1) * 2;
    const float *Abase = A + (size_t)(rowBase + ar) * lda;
    const int br = t >> 2;
    const float *Wrow = W + (size_t)(colBase + br) * K;

    const uint32_t sA = (uint32_t)__cvta_generic_to_shared(&As[0][0]);
    const uint32_t sB = (uint32_t)__cvta_generic_to_shared(&Bs[0][0]);
    const int bufAB = BM * BK * 4;
    const int bufBB = BN * BSTR * 4;

    ull acc[8][4];
#pragma unroll
    for (int i = 0; i < 8; i++)
#pragma unroll
        for (int j = 0; j < 4; j++) acc[i][j] = 0ULL;

    const int T = (K + BK - 1) / BK;
    auto issue = [&](int kt, int buf) {
#pragma unroll
        for (int u = 0; u < 2; ++u) {
            int ch = ac + u;
            int k0 = kt + ch * 4;
            int sb = clampi((K - k0) * 4, 0, 16);
            const float *src = sb > 0 ? (Abase + k0) : A;
            cpa16(sA + buf * bufAB + (ar * BK + ch * 4) * 4, src, sb);
        }
        {
            int ch = t & 3;
            int k0 = kt + ch * 4;
            int sb = clampi((K - k0) * 4, 0, 16);
            const float *src = sb > 0 ? (Wrow + k0) : W;
            cpa16(sB + buf * bufBB + (br * BSTR + ch * 4) * 4, src, sb);
        }
        cp_commit();
    };

    issue(0, 0);
    for (int it = 0; it < T; ++it) {
        cp_wait0();
        __syncthreads();
        if (it + 1 < T) issue((it + 1) * BK, (it + 1) & 1);
        const float *as = As[it & 1];
        const float *bs = Bs[it & 1];
#pragma unroll
        for (int k4 = 0; k4 < 4; ++k4) {
            ulonglong2 b[4];
#pragma unroll
            for (int j = 0; j < 4; ++j)
                b[j] = *(const ulonglong2 *)&bs[(tx + 16 * j) * BSTR + k4 * 4];
#pragma unroll
            for (int i = 0; i < 8; ++i) {
                ulonglong2 a = *(const ulonglong2 *)&as[(ty * 8 + i) * BK + k4 * 4];
#pragma unroll
                for (int j = 0; j < 4; ++j) {
                    ffma2(acc[i][j], a.x, b[j].x);
                    ffma2(acc[i][j], a.y, b[j].y);
                }
            }
        }
    }

    const float alpha = g_affine[2][0];
    const float beta = g_affine[2][1];
    int cc[4]; float effb[4];
#pragma unroll
    for (int j = 0; j < 4; ++j) {
        cc[j] = colBase + tx + 16 * j;
        effb[j] = bias[cc[j]] + beta * ws[cc[j]];
    }

    const size_t seg = (size_t)BATCH * FBDIM;
    const int r0 = rowBase + ty * 8;
#pragma unroll
    for (int i = 0; i < 8; ++i) {
        int r = r0 + i;
#pragma unroll
        for (int j = 0; j < 4; ++j) {
            float2 p = unpack2(acc[i][j]);
            float v = fmaf(alpha, p.x + p.y, effb[j]);
            float o = 1.f / (1.f + expf(-v));
            const float *cb = &cbs[(tx + 16 * j) * 8];
            float mind = 3.402823466e38f;
            float q = -3.402823466e38f;
#pragma unroll
            for (int e = 0; e < 8; e++) {
                float cv = cb[e];
                float df = o - cv;
                float d = df * df;
                if (d < mind) { mind = d; q = cv; }
                else if (d == mind) { q = fmaxf(q, cv); }
            }
            size_t idx = (size_t)r * FBDIM + cc[j];
            out[idx] = o + (q - o);
            out[seg + idx] = q;
            out[2 * seg + idx] = o;
        }
    }
}

// ---------------- launch ----------------
extern "C" void kernel_launch(void *const *d_in, const int *in_sizes, int n_in,
                              void *d_out, int out_size) {
    (void)in_sizes; (void)n_in; (void)out_size;
    const float *x = (const float *)d_in[0];
    const float *w[9], *bb[9];
    for (int i = 0; i < 9; i++) {
        w[i] = (const float *)d_in[1 + 2 * i];
        bb[i] = (const float *)d_in[2 + 2 * i];
    }
    const float *bn_g[3] = {(const float *)d_in[19], (const float *)d_in[21],
                            (const float *)d_in[23]};
    const float *bn_b[3] = {(const float *)d_in[20], (const float *)d_in[22],
                            (const float *)d_in[24]};
    const float *fc_w = (const float *)d_in[25];
    const float *fc_b = (const float *)d_in[26];
    const float *cbk = (const float *)d_in[27];
    float *out = (float *)d_out;

    float *c1, *c2, *c3, *cA, *cB, *wsum;
    cudaGetSymbolAddress((void **)&c1, g_c1);
    cudaGetSymbolAddress((void **)&c2, g_c2);
    cudaGetSymbolAddress((void **)&c3, g_c3);
    cudaGetSymbolAddress((void **)&cA, g_carA);
    cudaGetSymbolAddress((void **)&cB, g_carB);
    cudaGetSymbolAddress((void **)&wsum, g_ws);

    const dim3 thr(NTHR);
    auto grid = [](int N) { return dim3((N + BN - 1) / BN, BATCH / BM); };

    setup_kernel<<<1712, 128>>>(w[3], w[6], fc_w);

    // phase 1: 24 -> 300(out150) -> 150(out100) -> 50(out50)
    gemm_split_kernel<<<grid(300), thr>>>(x, 24, w[0], bb[0], nullptr, 24, 300, 150,
                                          c1, 300, cA, LDCARA, 0, -1, 1);
    gemm_split_kernel<<<grid(150), thr>>>(cA, LDCARA, w[1], bb[1], nullptr, 150, 150, 100,
                                          c1 + 150, 300, cB, LDCARB, 0, -1, 0);
    gemm_split_kernel<<<grid(50), thr>>>(cB, LDCARB, w[2], bb[2], nullptr, 50, 50, 50,
                                         c1 + 250, 300, nullptr, 0, 0, -1, 0);
    finalize_kernel<<<1, 1>>>(0, bn_g[0], bn_b[0], (double)BATCH * 300.0);

    // phase 2: 300 -> 600(out300) -> 300(out200) -> 100(out100)
    gemm_split_kernel<<<grid(600), thr>>>(c1, 300, w[3], bb[3], wsum, 300, 600, 300,
                                          c2, 600, cA, LDCARA, 1, 0, 1);
    gemm_split_kernel<<<grid(300), thr>>>(cA, LDCARA, w[4], bb[4], nullptr, 300, 300, 200,
                                          c2 + 300, 600, cB, LDCARB, 1, -1, 1);
    gemm_split_kernel<<<grid(100), thr>>>(cB, LDCARB, w[5], bb[5], nullptr, 100, 100, 100,
                                          c2 + 500, 600, nullptr, 0, 1, -1, 1);
    finalize_kernel<<<1, 1>>>(1, bn_g[1], bn_b[1], (double)BATCH * 600.0);

    // phase 3: 600 -> 600(out300) -> 300(out200) -> 100(out100)
    gemm_split_kernel<<<grid(600), thr>>>(c2, 600, w[6], bb[6], wsum + 600, 600, 600, 300,
                                          c3, 600, cA, LDCARA, 2, 1, 1);
    gemm_split_kernel<<<grid(300), thr>>>(cA, LDCARA, w[7], bb[7], nullptr, 300, 300, 200,
                                          c3 + 300, 600, cB, LDCARB, 2, -1, 1);
    gemm_split_kernel<<<grid(100), thr>>>(cB, LDCARB, w[8], bb[8], nullptr, 100, 100, 100,
                                          c3 + 500, 600, nullptr, 0, 2, -1, 1);
    finalize_kernel<<<1, 1>>>(2, bn_g[2], bn_b[2], (double)BATCH * 600.0);

    // fc + sigmoid + codebook quantize
    fc_quant_kernel<<<grid(FBDIM), thr>>>(c3, 600, fc_w, fc_b, wsum + 1200, cbk, out);
}

// round 5
// speedup vs baseline: 2.1863x; 1.0093x over previous
#include <cuda_runtime.h>
#include <math.h>
#include <stdint.h>

#define BATCH 32768
#define FBDIM 512
#define BM 128
#define BN 64
#define BK 16
#define BSTR 20   // Bs row stride in floats (bank-conflict-free for LDS.128)
#define NTHR 256
#define LDCARA 304
#define LDCARB 104

typedef unsigned long long ull;

// ---------------- scratch (device globals; no allocation allowed) ----------------
__device__ float g_c1[BATCH * 300];
__device__ float g_c2[BATCH * 600];
__device__ float g_c3[BATCH * 600];
__device__ float g_carA[BATCH * LDCARA];
__device__ float g_carB[BATCH * LDCARB];
__device__ double g_stats[3][2];
__device__ float g_ws[1712];   // rowsums: w3[0:600], w6[600:1200], fc[1200:1712]

// ---------------- helpers ----------------
__device__ __forceinline__ void ffma2(ull &c, ull a, ull b) {
    asm("fma.rn.f32x2 %0, %1, %2, %0;" : "+l"(c) : "l"(a), "l"(b));
}
__device__ __forceinline__ float2 unpack2(ull v) {
    float2 f;
    asm("mov.b64 {%0, %1}, %2;" : "=f"(f.x), "=f"(f.y) : "l"(v));
    return f;
}
__device__ __forceinline__ float mishf(float v) {
    float sp = v + log1pf(expf(-v));   // v >= 0 post-relu: stable
    return v * tanhf(sp);
}
__device__ __forceinline__ void cpa16(uint32_t dst, const float *src, int srcbytes) {
    asm volatile("cp.async.cg.shared.global [%0], [%1], 16, %2;\n"
                 :: "r"(dst), "l"(src), "r"(srcbytes));
}
__device__ __forceinline__ void cpa8(uint32_t dst, const float *src, int srcbytes) {
    asm volatile("cp.async.ca.shared.global [%0], [%1], 8, %2;\n"
                 :: "r"(dst), "l"(src), "r"(srcbytes));
}
__device__ __forceinline__ void cp_commit() {
    asm volatile("cp.async.commit_group;\n" ::: "memory");
}
__device__ __forceinline__ void cp_wait0() {
    asm volatile("cp.async.wait_group 0;\n" ::: "memory");
}
__device__ __forceinline__ void cp_wait1() {
    asm volatile("cp.async.wait_group 1;\n" ::: "memory");
}
__device__ __forceinline__ int clampi(int v, int lo, int hi) {
    return v < lo ? lo : (v > hi ? hi : v);
}

// compute folded-BN affine from stats (call from 1 thread; publish via smem)
__device__ __forceinline__ void bn_affine(int p, const float *g, const float *b,
                                          double cnt, float *out2) {
    double mean = g_stats[p][0] / cnt;
    double var = g_stats[p][1] / cnt - mean * mean;
    double al = (double)g[0] / sqrt(var + 1e-5);
    out2[0] = (float)al;
    out2[1] = (float)((double)b[0] - mean * al);
}

// ---------------- setup: zero stats + weight rowsums ----------------
__global__ void setup_kernel(const float *__restrict__ w3, const float *__restrict__ w6,
                             const float *__restrict__ wfc) {
    int b = blockIdx.x;
    if (b == 0 && threadIdx.x < 6) ((double *)g_stats)[threadIdx.x] = 0.0;
    const float *src; int K;
    if (b < 600)       { src = w3 + (size_t)b * 300;          K = 300; }
    else if (b < 1200) { src = w6 + (size_t)(b - 600) * 600;  K = 600; }
    else               { src = wfc + (size_t)(b - 1200) * 600; K = 600; }
    float s = 0.f;
    for (int k = threadIdx.x; k < K; k += 128) s += src[k];
#pragma unroll
    for (int o = 16; o; o >>= 1) s += __shfl_down_sync(0xffffffffu, s, o);
    __shared__ float sm[4];
    if ((threadIdx.x & 31) == 0) sm[threadIdx.x >> 5] = s;
    __syncthreads();
    if (threadIdx.x == 0) g_ws[b] = sm[0] + sm[1] + sm[2] + sm[3];
}

// ---------------- fused GEMM (3-stage cp.async) + relu + split + stats ----------------
__global__ __launch_bounds__(NTHR, 2) void gemm_split_kernel(
    const float *__restrict__ A, int lda,
    const float *__restrict__ W, const float *__restrict__ bias,
    const float *__restrict__ ws,
    int K, int N, int OUT,
    float *__restrict__ collect, int ldc,
    float *__restrict__ carry, int ldcar,
    int stats_phase, int aff_phase,
    const float *__restrict__ bng, const float *__restrict__ bnb, double aff_cnt,
    int useCp16) {
    __shared__ __align__(16) float As[3][BM * BK];
    __shared__ __align__(16) float Bs[3][BN * BSTR];
    __shared__ float saff[2];
    __shared__ float red[16];

    const int t = threadIdx.x;
    const int tx = t & 15;
    const int ty = t >> 4;
    const int rowBase = blockIdx.y * BM;
    const int colBase = blockIdx.x * BN;

    if (t == 0) {
        if (aff_phase >= 0) bn_affine(aff_phase, bng, bnb, aff_cnt, saff);
        else { saff[0] = 1.f; saff[1] = 0.f; }
    }

    // loader mapping
    const int ar = t >> 1;
    const int ac = (t & 1) * 2;
    const float *Abase = A + (size_t)(rowBase + ar) * lda;
    const int br = t >> 2;
    const int n_b = colBase + br;
    const bool bv = n_b < N;
    const float *Wrow = W + (size_t)(bv ? n_b : 0) * K;

    const uint32_t sA = (uint32_t)__cvta_generic_to_shared(&As[0][0]);
    const uint32_t sB = (uint32_t)__cvta_generic_to_shared(&Bs[0][0]);
    const int bufAB = BM * BK * 4;
    const int bufBB = BN * BSTR * 4;

    ull acc[8][4];
#pragma unroll
    for (int i = 0; i < 8; i++)
#pragma unroll
        for (int j = 0; j < 4; j++) acc[i][j] = 0ULL;

    const int T = (K + BK - 1) / BK;

    auto issue = [&](int kt, int buf) {
#pragma unroll
        for (int u = 0; u < 2; ++u) {
            int ch = ac + u;
            int k0 = kt + ch * 4;
            int sb = clampi((K - k0) * 4, 0, 16);
            const float *src = sb > 0 ? (Abase + k0) : A;
            cpa16(sA + buf * bufAB + (ar * BK + ch * 4) * 4, src, sb);
        }
        if (useCp16) {
            int ch = t & 3;
            int k0 = kt + ch * 4;
            int sb = bv ? clampi((K - k0) * 4, 0, 16) : 0;
            const float *src = sb > 0 ? (Wrow + k0) : W;
            cpa16(sB + buf * bufBB + (br * BSTR + ch * 4) * 4, src, sb);
        } else {
#pragma unroll
            for (int u = 0; u < 2; ++u) {
                int ch = (t & 3) * 2 + u;
                int k0 = kt + ch * 2;
                int sb = bv ? clampi((K - k0) * 4, 0, 8) : 0;
                const float *src = sb > 0 ? (Wrow + k0) : W;
                cpa8(sB + buf * bufBB + (br * BSTR + ch * 2) * 4, src, sb);
            }
        }
        cp_commit();
    };

    issue(0, 0);
    if (T > 1) issue(BK, 1);
    int buf = 0;
    for (int it = 0; it < T; ++it) {
        if (it < T - 1) cp_wait1(); else cp_wait0();
        __syncthreads();
        if (it + 2 < T) {
            int nb = buf + 2; if (nb >= 3) nb -= 3;
            issue((it + 2) * BK, nb);
        }
        const float *as = &As[buf][ty * 8 * BK];
        const float *bs = &Bs[buf][tx * BSTR];
#pragma unroll
        for (int k4 = 0; k4 < 4; ++k4) {
            ulonglong2 b[4];
#pragma unroll
            for (int j = 0; j < 4; ++j)
                b[j] = *(const ulonglong2 *)&bs[(16 * j) * BSTR + k4 * 4];
#pragma unroll
            for (int i = 0; i < 8; ++i) {
                ulonglong2 a = *(const ulonglong2 *)&as[i * BK + k4 * 4];
#pragma unroll
                for (int j = 0; j < 4; ++j) {
                    ffma2(acc[i][j], a.x, b[j].x);
                    ffma2(acc[i][j], a.y, b[j].y);
                }
            }
        }
        if (++buf >= 3) buf = 0;
    }

    // ---- epilogue ----
    const float alpha = saff[0];
    const float beta = saff[1];

    int cc[4]; bool cvl[4]; float effb[4];
#pragma unroll
    for (int j = 0; j < 4; ++j) {
        cc[j] = colBase + tx + 16 * j;
        cvl[j] = cc[j] < N;
        effb[j] = cvl[j] ? (bias[cc[j]] + (ws ? beta * ws[cc[j]] : 0.f)) : 0.f;
    }

    float lsum = 0.f, lsq = 0.f;
    const int r0 = rowBase + ty * 8;
#pragma unroll
    for (int i = 0; i < 8; ++i) {
        int r = r0 + i;
#pragma unroll
        for (int j = 0; j < 4; ++j) {
            if (!cvl[j]) continue;
            float2 p = unpack2(acc[i][j]);
            float v = fmaf(alpha, p.x + p.y, effb[j]);
            v = fmaxf(v, 0.f);
            if (cc[j] < OUT) {
                float m = mishf(v);
                collect[(size_t)r * ldc + cc[j]] = m;
                lsum += m;
                lsq = fmaf(m, m, lsq);
            } else {
                carry[(size_t)r * ldcar + (cc[j] - OUT)] = v;
            }
        }
    }

#pragma unroll
    for (int off = 16; off > 0; off >>= 1) {
        lsum += __shfl_down_sync(0xffffffffu, lsum, off);
        lsq += __shfl_down_sync(0xffffffffu, lsq, off);
    }
    if ((t & 31) == 0) { red[t >> 5] = lsum; red[8 + (t >> 5)] = lsq; }
    __syncthreads();
    if (t == 0) {
        float s = 0.f, q = 0.f;
#pragma unroll
        for (int w = 0; w < 8; w++) { s += red[w]; q += red[8 + w]; }
        atomicAdd(&g_stats[stats_phase][0], (double)s);
        atomicAdd(&g_stats[stats_phase][1], (double)q);
    }
}

// ---------------- final: fc (600->512) + sigmoid + codebook quantize ----------------
__global__ __launch_bounds__(NTHR, 2) void fc_quant_kernel(
    const float *__restrict__ A, int lda,
    const float *__restrict__ W, const float *__restrict__ bias,
    const float *__restrict__ ws,
    const float *__restrict__ codebook,
    const float *__restrict__ bng, const float *__restrict__ bnb,
    float *__restrict__ out) {
    __shared__ __align__(16) float As[3][BM * BK];
    __shared__ __align__(16) float Bs[3][BN * BSTR];
    __shared__ float cbs[BN * 8];
    __shared__ float saff[2];

    const int t = threadIdx.x;
    const int tx = t & 15;
    const int ty = t >> 4;
    const int rowBase = blockIdx.y * BM;
    const int colBase = blockIdx.x * BN;
    const int K = 600;

    if (t == 0) bn_affine(2, bng, bnb, (double)BATCH * 600.0, saff);
    for (int i = t; i < BN * 8; i += NTHR) cbs[i] = codebook[colBase * 8 + i];

    const int ar = t >> 1;
    const int ac = (t & 1) * 2;
    const float *Abase = A + (size_t)(rowBase + ar) * lda;
    const int br = t >> 2;
    const float *Wrow = W + (size_t)(colBase + br) * K;

    const uint32_t sA = (uint32_t)__cvta_generic_to_shared(&As[0][0]);
    const uint32_t sB = (uint32_t)__cvta_generic_to_shared(&Bs[0][0]);
    const int bufAB = BM * BK * 4;
    const int bufBB = BN * BSTR * 4;

    ull acc[8][4];
#pragma unroll
    for (int i = 0; i < 8; i++)
#pragma unroll
        for (int j = 0; j < 4; j++) acc[i][j] = 0ULL;

    const int T = (K + BK - 1) / BK;
    auto issue = [&](int kt, int buf) {
#pragma unroll
        for (int u = 0; u < 2; ++u) {
            int ch = ac + u;
            int k0 = kt + ch * 4;
            int sb = clampi((K - k0) * 4, 0, 16);
            const float *src = sb > 0 ? (Abase + k0) : A;
            cpa16(sA + buf * bufAB + (ar * BK + ch * 4) * 4, src, sb);
        }
        {
            int ch = t & 3;
            int k0 = kt + ch * 4;
            int sb = clampi((K - k0) * 4, 0, 16);
            const float *src = sb > 0 ? (Wrow + k0) : W;
            cpa16(sB + buf * bufBB + (br * BSTR + ch * 4) * 4, src, sb);
        }
        cp_commit();
    };

    issue(0, 0);
    issue(BK, 1);
    int buf = 0;
    for (int it = 0; it < T; ++it) {
        if (it < T - 1) cp_wait1(); else cp_wait0();
        __syncthreads();
        if (it + 2 < T) {
            int nb = buf + 2; if (nb >= 3) nb -= 3;
            issue((it + 2) * BK, nb);
        }
        const float *as = &As[buf][ty * 8 * BK];
        const float *bs = &Bs[buf][tx * BSTR];
#pragma unroll
        for (int k4 = 0; k4 < 4; ++k4) {
            ulonglong2 b[4];
#pragma unroll
            for (int j = 0; j < 4; ++j)
                b[j] = *(const ulonglong2 *)&bs[(16 * j) * BSTR + k4 * 4];
#pragma unroll
            for (int i = 0; i < 8; ++i) {
                ulonglong2 a = *(const ulonglong2 *)&as[i * BK + k4 * 4];
#pragma unroll
                for (int j = 0; j < 4; ++j) {
                    ffma2(acc[i][j], a.x, b[j].x);
                    ffma2(acc[i][j], a.y, b[j].y);
                }
            }
        }
        if (++buf >= 3) buf = 0;
    }

    const float alpha = saff[0];
    const float beta = saff[1];
    int cc[4]; float effb[4];
#pragma unroll
    for (int j = 0; j < 4; ++j) {
        cc[j] = colBase + tx + 16 * j;
        effb[j] = bias[cc[j]] + beta * ws[cc[j]];
    }

    const size_t seg = (size_t)BATCH * FBDIM;
    const int r0 = rowBase + ty * 8;
#pragma unroll
    for (int i = 0; i < 8; ++i) {
        int r = r0 + i;
#pragma unroll
        for (int j = 0; j < 4; ++j) {
            float2 p = unpack2(acc[i][j]);
            float v = fmaf(alpha, p.x + p.y, effb[j]);
            float o = 1.f / (1.f + expf(-v));
            const float *cb = &cbs[(tx + 16 * j) * 8];
            float mind = 3.402823466e38f;
            float q = -3.402823466e38f;
#pragma unroll
            for (int e = 0; e < 8; e++) {
                float cv = cb[e];
                float df = o - cv;
                float d = df * df;
                if (d < mind) { mind = d; q = cv; }
                else if (d == mind) { q = fmaxf(q, cv); }
            }
            size_t idx = (size_t)r * FBDIM + cc[j];
            out[idx] = o + (q - o);
            out[seg + idx] = q;
            out[2 * seg + idx] = o;
        }
    }
}

// ---------------- launch ----------------
extern "C" void kernel_launch(void *const *d_in, const int *in_sizes, int n_in,
                              void *d_out, int out_size) {
    (void)in_sizes; (void)n_in; (void)out_size;
    const float *x = (const float *)d_in[0];
    const float *w[9], *bb[9];
    for (int i = 0; i < 9; i++) {
        w[i] = (const float *)d_in[1 + 2 * i];
        bb[i] = (const float *)d_in[2 + 2 * i];
    }
    const float *bn_g[3] = {(const float *)d_in[19], (const float *)d_in[21],
                            (const float *)d_in[23]};
    const float *bn_b[3] = {(const float *)d_in[20], (const float *)d_in[22],
                            (const float *)d_in[24]};
    const float *fc_w = (const float *)d_in[25];
    const float *fc_b = (const float *)d_in[26];
    const float *cbk = (const float *)d_in[27];
    float *out = (float *)d_out;

    float *c1, *c2, *c3, *cA, *cB, *wsum;
    cudaGetSymbolAddress((void **)&c1, g_c1);
    cudaGetSymbolAddress((void **)&c2, g_c2);
    cudaGetSymbolAddress((void **)&c3, g_c3);
    cudaGetSymbolAddress((void **)&cA, g_carA);
    cudaGetSymbolAddress((void **)&cB, g_carB);
    cudaGetSymbolAddress((void **)&wsum, g_ws);

    const dim3 thr(NTHR);
    auto grid = [](int N) { return dim3((N + BN - 1) / BN, BATCH / BM); };
    const double cnt1 = (double)BATCH * 300.0;
    const double cnt2 = (double)BATCH * 600.0;

    setup_kernel<<<1712, 128>>>(w[3], w[6], fc_w);

    // phase 1
    gemm_split_kernel<<<grid(300), thr>>>(x, 24, w[0], bb[0], nullptr, 24, 300, 150,
                                          c1, 300, cA, LDCARA, 0, -1, nullptr, nullptr, 0.0, 1);
    gemm_split_kernel<<<grid(150), thr>>>(cA, LDCARA, w[1], bb[1], nullptr, 150, 150, 100,
                                          c1 + 150, 300, cB, LDCARB, 0, -1, nullptr, nullptr, 0.0, 0);
    gemm_split_kernel<<<grid(50), thr>>>(cB, LDCARB, w[2], bb[2], nullptr, 50, 50, 50,
                                         c1 + 250, 300, nullptr, 0, 0, -1, nullptr, nullptr, 0.0, 0);

    // phase 2 (BN1 folded into first GEMM's epilogue scaling)
    gemm_split_kernel<<<grid(600), thr>>>(c1, 300, w[3], bb[3], wsum, 300, 600, 300,
                                          c2, 600, cA, LDCARA, 1, 0, bn_g[0], bn_b[0], cnt1, 1);
    gemm_split_kernel<<<grid(300), thr>>>(cA, LDCARA, w[4], bb[4], nullptr, 300, 300, 200,
                                          c2 + 300, 600, cB, LDCARB, 1, -1, nullptr, nullptr, 0.0, 1);
    gemm_split_kernel<<<grid(100), thr>>>(cB, LDCARB, w[5], bb[5], nullptr, 100, 100, 100,
                                          c2 + 500, 600, nullptr, 0, 1, -1, nullptr, nullptr, 0.0, 1);

    // phase 3 (BN2 folded)
    gemm_split_kernel<<<grid(600), thr>>>(c2, 600, w[6], bb[6], wsum + 600, 600, 600, 300,
                                          c3, 600, cA, LDCARA, 2, 1, bn_g[1], bn_b[1], cnt2, 1);
    gemm_split_kernel<<<grid(300), thr>>>(cA, LDCARA, w[7], bb[7], nullptr, 300, 300, 200,
                                          c3 + 300, 600, cB, LDCARB, 2, -1, nullptr, nullptr, 0.0, 1);
    gemm_split_kernel<<<grid(100), thr>>>(cB, LDCARB, w[8], bb[8], nullptr, 100, 100, 100,
                                          c3 + 500, 600, nullptr, 0, 2, -1, nullptr, nullptr, 0.0, 1);

    // fc + sigmoid + codebook quantize (BN3 folded)
    fc_quant_kernel<<<grid(FBDIM), thr>>>(c3, 600, fc_w, fc_b, wsum + 1200, cbk,
                                          bn_g[2], bn_b[2], out);
}